// round 8
// baseline (speedup 1.0000x reference)
#include <cuda_runtime.h>
#include <cuda_bf16.h>
#include <math.h>
#include <stdint.h>

#define N_NODES  100000
#define N_EDGES  1600000
#define N_GRAPHS 2048
#define H        256

#define SCAN_NBLK ((N_NODES + 1023) / 1024)   // 98 blocks of 1024

// ---------------- scratch (device globals; no allocs allowed) ----------------
__device__ int   g_ideg[N_NODES];
__device__ int   g_off[N_NODES];
__device__ int   g_cursor[N_NODES];
__device__ int   g_csr[N_EDGES];
__device__ int   g_bsum[SCAN_NBLK];
__device__ int   g_bscan[SCAN_NBLK];
__device__ float g_dinv[N_NODES];
__device__ float g_gsum[N_GRAPHS * H];
__device__ float g_gcnt[N_GRAPHS];
// bf16 split operands for tensor-core GEMMs
__device__ __nv_bfloat16 g_z1h[(size_t)N_NODES * 128];  // S*x  (layer-1 agg out)
__device__ __nv_bfloat16 g_z1l[(size_t)N_NODES * 128];
__device__ __nv_bfloat16 g_h1h[(size_t)N_NODES * H];    // relu(z1*W1+b1)
__device__ __nv_bfloat16 g_h1l[(size_t)N_NODES * H];
__device__ __nv_bfloat16 g_z2h[(size_t)N_NODES * H];    // S*h1 (layer-2 agg out)
__device__ __nv_bfloat16 g_z2l[(size_t)N_NODES * H];
__device__ __nv_bfloat16 g_w1h[256 * 128];
__device__ __nv_bfloat16 g_w1l[256 * 128];
__device__ __nv_bfloat16 g_w2h[256 * 256];
__device__ __nv_bfloat16 g_w2l[256 * 256];

// ================= warp-MMA helpers (sm_80-class, compile for compute_103) ==
__device__ __forceinline__ uint32_t smem_u32(const void* p) {
    uint32_t a;
    asm("{ .reg .u64 t; cvta.to.shared.u64 t, %1; cvt.u32.u64 %0, t; }" : "=r"(a) : "l"(p));
    return a;
}
__device__ __forceinline__ void ldm_x4(uint32_t* r, uint32_t addr) {
    asm volatile("ldmatrix.sync.aligned.m8n8.x4.shared.b16 {%0,%1,%2,%3}, [%4];"
                 : "=r"(r[0]), "=r"(r[1]), "=r"(r[2]), "=r"(r[3]) : "r"(addr));
}
__device__ __forceinline__ void mma16816(float* d, const uint32_t* a, const uint32_t* b) {
    asm volatile("mma.sync.aligned.m16n8k16.row.col.f32.bf16.bf16.f32 "
                 "{%0,%1,%2,%3}, {%4,%5,%6,%7}, {%8,%9}, {%0,%1,%2,%3};"
                 : "+f"(d[0]), "+f"(d[1]), "+f"(d[2]), "+f"(d[3])
                 : "r"(a[0]), "r"(a[1]), "r"(a[2]), "r"(a[3]), "r"(b[0]), "r"(b[1]));
}
__device__ __forceinline__ void cp16(uint32_t dst, const void* src) {
    asm volatile("cp.async.ca.shared.global [%0], [%1], 16;" :: "r"(dst), "l"(src));
}
#define CP_COMMIT() asm volatile("cp.async.commit_group;" ::: "memory")
#define CP_WAIT1()  asm volatile("cp.async.wait_group 1;" ::: "memory")
#define CP_WAIT0()  asm volatile("cp.async.wait_group 0;" ::: "memory")

__device__ __forceinline__ void split2(float a, float b, __nv_bfloat162* ph, __nv_bfloat162* pl) {
    __nv_bfloat16 ha = __float2bfloat16(a);
    __nv_bfloat16 hb = __float2bfloat16(b);
    __nv_bfloat16 la = __float2bfloat16(a - __bfloat162float(ha));
    __nv_bfloat16 lb = __float2bfloat16(b - __bfloat162float(hb));
    *ph = __halves2bfloat162(ha, hb);
    *pl = __halves2bfloat162(la, lb);
}

// ---------------- prep kernels ----------------

__global__ void zero_kernel() {
    int i = blockIdx.x * blockDim.x + threadIdx.x;     // grid covers N_GRAPHS*H = 524288
    if (i < N_NODES) { g_ideg[i] = 0; g_cursor[i] = 0; }
    if (i < N_GRAPHS * H) g_gsum[i] = 0.f;
    if (i < N_GRAPHS)     g_gcnt[i] = 0.f;
}

__global__ void deg_kernel(const int* __restrict__ dst) {
    int e = blockIdx.x * blockDim.x + threadIdx.x;
    if (e < N_EDGES) atomicAdd(&g_ideg[dst[e]], 1);
}

__global__ void scan1_kernel() {
    __shared__ int sh[256];
    int tid = threadIdx.x;
    int base = blockIdx.x * 1024 + tid * 4;
    int v[4]; int s = 0;
#pragma unroll
    for (int k = 0; k < 4; ++k) {
        int i = base + k;
        v[k] = (i < N_NODES) ? g_ideg[i] : 0;
        s += v[k];
    }
    sh[tid] = s; __syncthreads();
#pragma unroll
    for (int o = 1; o < 256; o <<= 1) {
        int t = (tid >= o) ? sh[tid - o] : 0;
        __syncthreads(); sh[tid] += t; __syncthreads();
    }
    int run = sh[tid] - s;
#pragma unroll
    for (int k = 0; k < 4; ++k) {
        int i = base + k;
        if (i < N_NODES) g_off[i] = run;
        run += v[k];
    }
    if (tid == 255) g_bsum[blockIdx.x] = sh[255];
}

__global__ void scan2_kernel() {
    __shared__ int sh[128];
    int tid = threadIdx.x;
    int v = (tid < SCAN_NBLK) ? g_bsum[tid] : 0;
    sh[tid] = v; __syncthreads();
#pragma unroll
    for (int o = 1; o < 128; o <<= 1) {
        int t = (tid >= o) ? sh[tid - o] : 0;
        __syncthreads(); sh[tid] += t; __syncthreads();
    }
    if (tid < SCAN_NBLK) g_bscan[tid] = sh[tid] - v;
}

__global__ void scan3_kernel() {
    int i = blockIdx.x * blockDim.x + threadIdx.x;
    if (i < N_NODES) g_off[i] += g_bscan[i >> 10];
}

__global__ void fill_kernel(const int* __restrict__ src, const int* __restrict__ dst) {
    int e = blockIdx.x * blockDim.x + threadIdx.x;
    if (e < N_EDGES) {
        int d = dst[e];
        int pos = g_off[d] + atomicAdd(&g_cursor[d], 1);
        g_csr[pos] = src[e];
    }
}

__global__ void prep_kernel(const int* __restrict__ batch) {
    int i = blockIdx.x * blockDim.x + threadIdx.x;
    if (i < N_NODES) {
        g_dinv[i] = rsqrtf((float)g_ideg[i] + 1.0f);
        atomicAdd(&g_gcnt[batch[i]], 1.0f);
    }
}

// transpose + split W[K,256] -> Wt hi/lo [256,K] bf16
__global__ void split_w_kernel(const float* __restrict__ W,
                               __nv_bfloat16* __restrict__ Th,
                               __nv_bfloat16* __restrict__ Tl, int K) {
    int i = blockIdx.x * blockDim.x + threadIdx.x;     // K*256 threads
    if (i < K * 256) {
        int k = i >> 8;
        int n = i & 255;
        float w = W[i];                 // coalesced read
        __nv_bfloat16 h = __float2bfloat16(w);
        Th[n * K + k] = h;
        Tl[n * K + k] = __float2bfloat16(w - __bfloat162float(h));
    }
}

// ---------------- layer-1 aggregation on raw x (pull-model CSR gather) -------
// z1[d] = dinv[d] * ( sum_{s in N(d)} dinv[s]*x[s] + dinv[d]*x[d] )  -> split bf16
// One warp per node, 128 cols (one float4 per lane).
__global__ void __launch_bounds__(256)
agg1_kernel(const float* __restrict__ x)
{
    int warp = threadIdx.x >> 5;
    int lane = threadIdx.x & 31;
    int node = blockIdx.x * 8 + warp;          // grid.x = 12500, exact
    int coff = lane * 4;

    float dvd = g_dinv[node];
    float4 xs = *(const float4*)(x + (size_t)node * 128 + coff);
    float4 acc;
    acc.x = xs.x * dvd; acc.y = xs.y * dvd; acc.z = xs.z * dvd; acc.w = xs.w * dvd;

    int beg = g_off[node];
    int cnt = g_ideg[node];
    const int* nb = g_csr + beg;
    for (int j = 0; j < cnt; ++j) {
        int s = nb[j];
        float ds = g_dinv[s];
        float4 v = *(const float4*)(x + (size_t)s * 128 + coff);
        acc.x = fmaf(v.x, ds, acc.x);
        acc.y = fmaf(v.y, ds, acc.y);
        acc.z = fmaf(v.z, ds, acc.z);
        acc.w = fmaf(v.w, ds, acc.w);
    }
    acc.x *= dvd; acc.y *= dvd; acc.z *= dvd; acc.w *= dvd;

    size_t base = (size_t)node * 128 + coff;
    __nv_bfloat162 h0, l0, h1, l1;
    split2(acc.x, acc.y, &h0, &l0);
    split2(acc.z, acc.w, &h1, &l1);
    ((__nv_bfloat162*)(g_z1h + base))[0] = h0;
    ((__nv_bfloat162*)(g_z1h + base))[1] = h1;
    ((__nv_bfloat162*)(g_z1l + base))[0] = l0;
    ((__nv_bfloat162*)(g_z1l + base))[1] = l1;
}

// ---------------- layer-2 aggregation on h1 (bf16 hi/lo pairs) ---------------
// z2[d] = dinv[d] * ( sum dinv[s]*h1[s] + dinv[d]*h1[d] ) -> split bf16
__global__ void __launch_bounds__(256)
agg2_kernel()
{
    int warp = threadIdx.x >> 5;
    int lane = threadIdx.x & 31;
    int node = blockIdx.x * 8 + warp;          // grid.x = 12500
    int coff = blockIdx.y * 128 + lane * 4;    // 2 chunks of 128

    float dvd = g_dinv[node];
    size_t sbase = (size_t)node * H + coff;
    // reconstruct h1 = hi + lo
    float4 f;
    {
        __nv_bfloat162 a0 = ((const __nv_bfloat162*)(g_h1h + sbase))[0];
        __nv_bfloat162 a1 = ((const __nv_bfloat162*)(g_h1h + sbase))[1];
        __nv_bfloat162 b0 = ((const __nv_bfloat162*)(g_h1l + sbase))[0];
        __nv_bfloat162 b1 = ((const __nv_bfloat162*)(g_h1l + sbase))[1];
        f.x = __bfloat162float(__low2bfloat16(a0))  + __bfloat162float(__low2bfloat16(b0));
        f.y = __bfloat162float(__high2bfloat16(a0)) + __bfloat162float(__high2bfloat16(b0));
        f.z = __bfloat162float(__low2bfloat16(a1))  + __bfloat162float(__low2bfloat16(b1));
        f.w = __bfloat162float(__high2bfloat16(a1)) + __bfloat162float(__high2bfloat16(b1));
    }
    float4 acc;
    acc.x = f.x * dvd; acc.y = f.y * dvd; acc.z = f.z * dvd; acc.w = f.w * dvd;

    int beg = g_off[node];
    int cnt = g_ideg[node];
    const int* nb = g_csr + beg;
    for (int j = 0; j < cnt; ++j) {
        int s = nb[j];
        float ds = g_dinv[s];
        size_t sb2 = (size_t)s * H + coff;
        __nv_bfloat162 a0 = ((const __nv_bfloat162*)(g_h1h + sb2))[0];
        __nv_bfloat162 a1 = ((const __nv_bfloat162*)(g_h1h + sb2))[1];
        __nv_bfloat162 b0 = ((const __nv_bfloat162*)(g_h1l + sb2))[0];
        __nv_bfloat162 b1 = ((const __nv_bfloat162*)(g_h1l + sb2))[1];
        float vx = __bfloat162float(__low2bfloat16(a0))  + __bfloat162float(__low2bfloat16(b0));
        float vy = __bfloat162float(__high2bfloat16(a0)) + __bfloat162float(__high2bfloat16(b0));
        float vz = __bfloat162float(__low2bfloat16(a1))  + __bfloat162float(__low2bfloat16(b1));
        float vw = __bfloat162float(__high2bfloat16(a1)) + __bfloat162float(__high2bfloat16(b1));
        acc.x = fmaf(vx, ds, acc.x);
        acc.y = fmaf(vy, ds, acc.y);
        acc.z = fmaf(vz, ds, acc.z);
        acc.w = fmaf(vw, ds, acc.w);
    }
    acc.x *= dvd; acc.y *= dvd; acc.z *= dvd; acc.w *= dvd;

    __nv_bfloat162 h0, l0, h1v, l1v;
    split2(acc.x, acc.y, &h0, &l0);
    split2(acc.z, acc.w, &h1v, &l1v);
    ((__nv_bfloat162*)(g_z2h + sbase))[0] = h0;
    ((__nv_bfloat162*)(g_z2h + sbase))[1] = h1v;
    ((__nv_bfloat162*)(g_z2l + sbase))[0] = l0;
    ((__nv_bfloat162*)(g_z2l + sbase))[1] = l1v;
}

// ======== tensor-core GEMM (mma.sync bf16, fused 3x precision split) ========
// A (hi/lo): [M, K] bf16 row-major.  Wt (hi/lo): [256, K] bf16 row-major.
// out = relu(A@Wt^T + bias).  mode 0: write split bf16 to outH/outL.
//                             mode 1: red.add into gsum[batch[row]].
#define ST_AH 0
#define ST_AL 16384
#define ST_BH 32768
#define ST_BL 49152
#define STAGE 65536
#define GEMM_SMEM (2 * STAGE)   // 131072

__global__ void __launch_bounds__(256, 1)
gemm_tc(const __nv_bfloat16* __restrict__ Ah, const __nv_bfloat16* __restrict__ Al,
        const __nv_bfloat16* __restrict__ Bh, const __nv_bfloat16* __restrict__ Bl,
        const float* __restrict__ bias,
        __nv_bfloat16* __restrict__ outH, __nv_bfloat16* __restrict__ outL,
        const int* __restrict__ batch, float* __restrict__ gsum,
        int M, int K, int mode)
{
    extern __shared__ __align__(128) char smem[];
    const uint32_t sb = smem_u32(smem);
    const int tid = threadIdx.x;
    const int wid = tid >> 5;
    const int lane = tid & 31;
    const int tile0 = blockIdx.x * 128;      // M block
    const int nb = blockIdx.y * 128;         // N block

    const int kcn = K >> 6;

    const int lrow   = tid >> 3;
    const int dstx   = ((tid & 7) << 4) ^ ((lrow & 7) << 4);
    const int colelm = (tid & 7) << 3;

    const int warp_m = wid & 1;
    const int warp_n = wid >> 1;
    const int arow  = warp_m * 64 + (lane & 15);
    const int axor  = (lane & 7) << 4;
    const int ac8   = (lane >> 4) << 4;
    const int brow  = warp_n * 32 + (lane & 7) + ((lane & 16) >> 1);
    const int bxor  = (lane & 7) << 4;
    const int bc8   = ((lane >> 3) & 1) << 4;

    float acc[4][4][4];
#pragma unroll
    for (int i = 0; i < 4; ++i)
#pragma unroll
        for (int j = 0; j < 4; ++j)
#pragma unroll
            for (int q = 0; q < 4; ++q) acc[i][j][q] = 0.f;

    auto load_stage = [&](int kc, int st) {
        const int kofs = (kc << 6) + colelm;
        uint32_t base = sb + st * STAGE;
#pragma unroll
        for (int j = 0; j < 4; ++j) {
            int row = lrow + (j << 5);
            int gr = tile0 + row; if (gr >= M) gr = M - 1;
            uint32_t rb = base + row * 128 + dstx;
            cp16(rb + ST_AH, Ah + (size_t)gr * K + kofs);
            cp16(rb + ST_AL, Al + (size_t)gr * K + kofs);
            cp16(rb + ST_BH, Bh + (size_t)(nb + row) * K + kofs);
            cp16(rb + ST_BL, Bl + (size_t)(nb + row) * K + kofs);
        }
    };

    load_stage(0, 0);
    CP_COMMIT();

    for (int ch = 0; ch < kcn; ++ch) {
        int st = ch & 1;
        if (ch + 1 < kcn) {
            load_stage(ch + 1, st ^ 1);
            CP_COMMIT();
            CP_WAIT1();
        } else {
            CP_WAIT0();
        }
        __syncthreads();

        uint32_t base = sb + st * STAGE;
#pragma unroll
        for (int p = 0; p < 3; ++p) {
            uint32_t Abase = base + ((p == 2) ? ST_AL : ST_AH);
            uint32_t Bbase = base + ((p == 1) ? ST_BL : ST_BH);
#pragma unroll
            for (int k16 = 0; k16 < 4; ++k16) {
                uint32_t a[4][4], b[2][4];
                int cA = ((k16 << 5) + ac8) ^ axor;
                uint32_t aaddr = Abase + arow * 128 + cA;
#pragma unroll
                for (int tm = 0; tm < 4; ++tm) ldm_x4(a[tm], aaddr + tm * 2048);
                int cB = ((k16 << 5) + bc8) ^ bxor;
                uint32_t baddr = Bbase + brow * 128 + cB;
#pragma unroll
                for (int t2 = 0; t2 < 2; ++t2) ldm_x4(b[t2], baddr + t2 * 2048);
#pragma unroll
                for (int tm = 0; tm < 4; ++tm)
#pragma unroll
                    for (int tn = 0; tn < 4; ++tn)
                        mma16816(acc[tm][tn], a[tm], &b[tn >> 1][(tn & 1) * 2]);
            }
        }
        __syncthreads();
    }

    // ---- epilogue: +bias, relu, then split-store or pool-reduce
    const int mrow0 = tile0 + warp_m * 64 + (lane >> 2);
    const int ncol0 = nb + warp_n * 32 + (lane & 3) * 2;
#pragma unroll
    for (int tm = 0; tm < 4; ++tm) {
        int r0 = mrow0 + tm * 16;
        int r1 = r0 + 8;
#pragma unroll
        for (int tn = 0; tn < 4; ++tn) {
            int c = ncol0 + tn * 8;
            const float2 bb = *(const float2*)(bias + c);
            float v0 = fmaxf(acc[tm][tn][0] + bb.x, 0.f);
            float v1 = fmaxf(acc[tm][tn][1] + bb.y, 0.f);
            float v2 = fmaxf(acc[tm][tn][2] + bb.x, 0.f);
            float v3 = fmaxf(acc[tm][tn][3] + bb.y, 0.f);
            if (mode == 0) {
                if (r0 < M) {
                    __nv_bfloat162 h, l;
                    split2(v0, v1, &h, &l);
                    *(__nv_bfloat162*)(outH + (size_t)r0 * H + c) = h;
                    *(__nv_bfloat162*)(outL + (size_t)r0 * H + c) = l;
                }
                if (r1 < M) {
                    __nv_bfloat162 h, l;
                    split2(v2, v3, &h, &l);
                    *(__nv_bfloat162*)(outH + (size_t)r1 * H + c) = h;
                    *(__nv_bfloat162*)(outL + (size_t)r1 * H + c) = l;
                }
            } else {
                if (r0 < M) {
                    float* p = gsum + (size_t)batch[r0] * H + c;
                    asm volatile("red.global.add.v2.f32 [%0], {%1, %2};"
                                 :: "l"(p), "f"(v0), "f"(v1) : "memory");
                }
                if (r1 < M) {
                    float* p = gsum + (size_t)batch[r1] * H + c;
                    asm volatile("red.global.add.v2.f32 [%0], {%1, %2};"
                                 :: "l"(p), "f"(v2), "f"(v3) : "memory");
                }
            }
        }
    }
}

// ---------------- classifier: mean, g@Wc+bc, log_softmax(64) ----------------
__global__ void classify_kernel(const float* __restrict__ gsum, const float* __restrict__ gcnt,
                                const float* __restrict__ Wc, const float* __restrict__ bc,
                                float* __restrict__ out)
{
    int gid = blockIdx.x;
    int j = threadIdx.x;                       // 64 threads
    __shared__ float sg[H];
    __shared__ float red2[2];

    float inv = 1.0f / fmaxf(gcnt[gid], 1.0f);
    for (int c = j; c < H; c += 64) sg[c] = gsum[(size_t)gid * H + c] * inv;
    __syncthreads();

    float acc = bc[j];
#pragma unroll
    for (int c = 0; c < H; ++c)
        acc = fmaf(sg[c], Wc[c * 64 + j], acc);

    float m = acc;
#pragma unroll
    for (int o = 16; o; o >>= 1) m = fmaxf(m, __shfl_xor_sync(0xffffffffu, m, o));
    if ((j & 31) == 0) red2[j >> 5] = m;
    __syncthreads();
    m = fmaxf(red2[0], red2[1]);
    __syncthreads();

    float e = expf(acc - m);
    float s = e;
#pragma unroll
    for (int o = 16; o; o >>= 1) s += __shfl_xor_sync(0xffffffffu, s, o);
    if ((j & 31) == 0) red2[j >> 5] = s;
    __syncthreads();
    s = red2[0] + red2[1];

    out[(size_t)gid * 64 + j] = acc - m - logf(s);
}

// ---------------- launch ----------------
extern "C" void kernel_launch(void* const* d_in, const int* in_sizes, int n_in,
                              void* d_out, int out_size)
{
    const float* x     = (const float*)d_in[0];
    const int*   eidx  = (const int*)d_in[1];     // int32 (JAX canonicalized)
    const int*   batch = (const int*)d_in[2];
    const float* W1    = (const float*)d_in[3];
    const float* b1    = (const float*)d_in[4];
    const float* W2    = (const float*)d_in[5];
    const float* b2    = (const float*)d_in[6];
    const float* Wc    = (const float*)d_in[7];
    const float* bc    = (const float*)d_in[8];
    float*       out   = (float*)d_out;

    const int* src = eidx;
    const int* dst = eidx + N_EDGES;

    float *gsum, *gcnt;
    __nv_bfloat16 *z1h, *z1l, *h1h, *h1l, *z2h, *z2l, *w1h, *w1l, *w2h, *w2l;
    cudaGetSymbolAddress((void**)&gsum, g_gsum);
    cudaGetSymbolAddress((void**)&gcnt, g_gcnt);
    cudaGetSymbolAddress((void**)&z1h, g_z1h);
    cudaGetSymbolAddress((void**)&z1l, g_z1l);
    cudaGetSymbolAddress((void**)&h1h, g_h1h);
    cudaGetSymbolAddress((void**)&h1l, g_h1l);
    cudaGetSymbolAddress((void**)&z2h, g_z2h);
    cudaGetSymbolAddress((void**)&z2l, g_z2l);
    cudaGetSymbolAddress((void**)&w1h, g_w1h);
    cudaGetSymbolAddress((void**)&w1l, g_w1l);
    cudaGetSymbolAddress((void**)&w2h, g_w2h);
    cudaGetSymbolAddress((void**)&w2l, g_w2l);

    cudaFuncSetAttribute(gemm_tc, cudaFuncAttributeMaxDynamicSharedMemorySize, GEMM_SMEM);

    // prep + CSR build
    zero_kernel<<<(N_GRAPHS * H) / 256, 256>>>();
    deg_kernel<<<(N_EDGES + 255) / 256, 256>>>(dst);
    scan1_kernel<<<SCAN_NBLK, 256>>>();
    scan2_kernel<<<1, 128>>>();
    scan3_kernel<<<(N_NODES + 255) / 256, 256>>>();
    fill_kernel<<<(N_EDGES + 255) / 256, 256>>>(src, dst);
    prep_kernel<<<(N_NODES + 255) / 256, 256>>>(batch);

    // weight splits
    split_w_kernel<<<(128 * 256 + 255) / 256, 256>>>(W1, w1h, w1l, 128);
    split_w_kernel<<<(256 * 256 + 255) / 256, 256>>>(W2, w2h, w2l, 256);

    const int ntiles = (N_NODES + 127) / 128;   // 782
    dim3 ggrid(ntiles, 2);
    dim3 a2grid(N_NODES / 8, 2);

    // layer 1: aggregate raw x first (associativity), then GEMM w/ relu+split epilogue
    agg1_kernel<<<N_NODES / 8, 256>>>(x);
    gemm_tc<<<ggrid, 256, GEMM_SMEM>>>(z1h, z1l, w1h, w1l, b1, h1h, h1l,
                                       nullptr, nullptr, N_NODES, 128, 0);

    // layer 2: aggregate h1 (bf16 pairs), GEMM w/ relu + fused mean-pool epilogue
    agg2_kernel<<<a2grid, 256>>>();
    gemm_tc<<<ggrid, 256, GEMM_SMEM>>>(z2h, z2l, w2h, w2l, b2, nullptr, nullptr,
                                       batch, gsum, N_NODES, 256, 1);

    // classifier + log_softmax
    classify_kernel<<<N_GRAPHS, 64>>>(gsum, gcnt, Wc, bc, out);
}

// round 9
// speedup vs baseline: 1.2711x; 1.2711x over previous
#include <cuda_runtime.h>
#include <cuda_fp16.h>
#include <math.h>
#include <stdint.h>

#define N_NODES  100000
#define N_EDGES  1600000
#define N_GRAPHS 2048
#define H        256

#define SCAN_NBLK ((N_NODES + 1023) / 1024)   // 98 blocks of 1024

// ---------------- scratch (device globals; no allocs allowed) ----------------
__device__ int   g_ideg[N_NODES];
__device__ int   g_off[N_NODES];
__device__ int   g_cursor[N_NODES];
__device__ int   g_csr[N_EDGES];
__device__ int   g_bsum[SCAN_NBLK];
__device__ int   g_bscan[SCAN_NBLK];
__device__ float g_dinv[N_NODES];
__device__ float g_bufA[(size_t)N_NODES * H];   // hs = (h @ W) * dinv[row]  (f32)
__device__ float g_gsum[N_GRAPHS * H];
__device__ float g_gcnt[N_GRAPHS];
// fp16 split operands for tensor-core GEMMs (A = hi+lo; W = single fp16)
__device__ __half g_xh[(size_t)N_NODES * 128];
__device__ __half g_xl[(size_t)N_NODES * 128];
__device__ __half g_h1h[(size_t)N_NODES * H];
__device__ __half g_h1l[(size_t)N_NODES * H];
__device__ __half g_w1[256 * 128];
__device__ __half g_w2[256 * 256];

// ================= warp-MMA helpers (sm_80-class, compile for compute_103) ==
__device__ __forceinline__ uint32_t smem_u32(const void* p) {
    uint32_t a;
    asm("{ .reg .u64 t; cvta.to.shared.u64 t, %1; cvt.u32.u64 %0, t; }" : "=r"(a) : "l"(p));
    return a;
}
__device__ __forceinline__ void ldm_x4(uint32_t* r, uint32_t addr) {
    asm volatile("ldmatrix.sync.aligned.m8n8.x4.shared.b16 {%0,%1,%2,%3}, [%4];"
                 : "=r"(r[0]), "=r"(r[1]), "=r"(r[2]), "=r"(r[3]) : "r"(addr));
}
__device__ __forceinline__ void mma16816(float* d, const uint32_t* a, const uint32_t* b) {
    asm volatile("mma.sync.aligned.m16n8k16.row.col.f32.f16.f16.f32 "
                 "{%0,%1,%2,%3}, {%4,%5,%6,%7}, {%8,%9}, {%0,%1,%2,%3};"
                 : "+f"(d[0]), "+f"(d[1]), "+f"(d[2]), "+f"(d[3])
                 : "r"(a[0]), "r"(a[1]), "r"(a[2]), "r"(a[3]), "r"(b[0]), "r"(b[1]));
}
__device__ __forceinline__ void cp16(uint32_t dst, const void* src) {
    asm volatile("cp.async.ca.shared.global [%0], [%1], 16;" :: "r"(dst), "l"(src));
}
#define CP_COMMIT() asm volatile("cp.async.commit_group;" ::: "memory")
#define CP_WAIT1()  asm volatile("cp.async.wait_group 1;" ::: "memory")
#define CP_WAIT0()  asm volatile("cp.async.wait_group 0;" ::: "memory")

__device__ __forceinline__ void split2h(float a, float b, __half2* ph, __half2* pl) {
    __half ha = __float2half_rn(a);
    __half hb = __float2half_rn(b);
    __half la = __float2half_rn(a - __half2float(ha));
    __half lb = __float2half_rn(b - __half2float(hb));
    *ph = __halves2half2(ha, hb);
    *pl = __halves2half2(la, lb);
}

// ---------------- prep kernels ----------------

__global__ void zero_kernel() {
    int i = blockIdx.x * blockDim.x + threadIdx.x;     // grid covers N_GRAPHS*H = 524288
    if (i < N_NODES) { g_ideg[i] = 0; g_cursor[i] = 0; }
    if (i < N_GRAPHS * H) g_gsum[i] = 0.f;
    if (i < N_GRAPHS)     g_gcnt[i] = 0.f;
}

__global__ void deg_kernel(const int* __restrict__ dst) {
    int e = blockIdx.x * blockDim.x + threadIdx.x;
    if (e < N_EDGES) atomicAdd(&g_ideg[dst[e]], 1);
}

__global__ void scan1_kernel() {
    __shared__ int sh[256];
    int tid = threadIdx.x;
    int base = blockIdx.x * 1024 + tid * 4;
    int v[4]; int s = 0;
#pragma unroll
    for (int k = 0; k < 4; ++k) {
        int i = base + k;
        v[k] = (i < N_NODES) ? g_ideg[i] : 0;
        s += v[k];
    }
    sh[tid] = s; __syncthreads();
#pragma unroll
    for (int o = 1; o < 256; o <<= 1) {
        int t = (tid >= o) ? sh[tid - o] : 0;
        __syncthreads(); sh[tid] += t; __syncthreads();
    }
    int run = sh[tid] - s;
#pragma unroll
    for (int k = 0; k < 4; ++k) {
        int i = base + k;
        if (i < N_NODES) g_off[i] = run;
        run += v[k];
    }
    if (tid == 255) g_bsum[blockIdx.x] = sh[255];
}

__global__ void scan2_kernel() {
    __shared__ int sh[128];
    int tid = threadIdx.x;
    int v = (tid < SCAN_NBLK) ? g_bsum[tid] : 0;
    sh[tid] = v; __syncthreads();
#pragma unroll
    for (int o = 1; o < 128; o <<= 1) {
        int t = (tid >= o) ? sh[tid - o] : 0;
        __syncthreads(); sh[tid] += t; __syncthreads();
    }
    if (tid < SCAN_NBLK) g_bscan[tid] = sh[tid] - v;
}

__global__ void scan3_kernel() {
    int i = blockIdx.x * blockDim.x + threadIdx.x;
    if (i < N_NODES) g_off[i] += g_bscan[i >> 10];
}

__global__ void fill_kernel(const int* __restrict__ src, const int* __restrict__ dst) {
    int e = blockIdx.x * blockDim.x + threadIdx.x;
    if (e < N_EDGES) {
        int d = dst[e];
        int pos = g_off[d] + atomicAdd(&g_cursor[d], 1);
        g_csr[pos] = src[e];
    }
}

__global__ void prep_kernel(const int* __restrict__ batch) {
    int i = blockIdx.x * blockDim.x + threadIdx.x;
    if (i < N_NODES) {
        g_dinv[i] = rsqrtf((float)g_ideg[i] + 1.0f);
        atomicAdd(&g_gcnt[batch[i]], 1.0f);
    }
}

// split x (f32) -> hi/lo fp16; one float4 per thread
__global__ void split_x_kernel(const float* __restrict__ x) {
    int i = blockIdx.x * blockDim.x + threadIdx.x;     // N_NODES*128/4 threads exactly
    float4 v = ((const float4*)x)[i];
    __half2 h0, l0, h1, l1;
    split2h(v.x, v.y, &h0, &l0);
    split2h(v.z, v.w, &h1, &l1);
    ((__half2*)g_xh)[i * 2 + 0] = h0;
    ((__half2*)g_xh)[i * 2 + 1] = h1;
    ((__half2*)g_xl)[i * 2 + 0] = l0;
    ((__half2*)g_xl)[i * 2 + 1] = l1;
}

// transpose W[K,256] -> Wt [256,K] single fp16
__global__ void split_w_kernel(const float* __restrict__ W,
                               __half* __restrict__ T, int K) {
    int i = blockIdx.x * blockDim.x + threadIdx.x;     // K*256 threads
    if (i < K * 256) {
        int k = i >> 8;
        int n = i & 255;
        T[n * K + k] = __float2half_rn(W[i]);          // coalesced read
    }
}

// ======== tensor-core GEMM (mma.sync fp16, 2-pass A-split) ==================
// A (hi/lo): [M, K] fp16 row-major.  Wt: [256, K] fp16 row-major.
// C[M, 256] f32 = (A @ Wt^T) * dinv[row].
// CTA tile 128x128, BK=64, double-buffered cp.async; 2 MMA passes (Ah*B, Al*B).
#define ST_AH 0
#define ST_AL 16384
#define ST_B  32768
#define STAGE 49152
#define GEMM_SMEM (2 * STAGE)   // 98304 -> 2 CTAs/SM possible

__global__ void __launch_bounds__(256, 2)
gemm_tc(const __half* __restrict__ Ah, const __half* __restrict__ Al,
        const __half* __restrict__ Bf,
        const float* __restrict__ dinv, float* __restrict__ C, int M, int K)
{
    extern __shared__ __align__(128) char smem[];
    const uint32_t sb = smem_u32(smem);
    const int tid = threadIdx.x;
    const int wid = tid >> 5;
    const int lane = tid & 31;
    const int tile0 = blockIdx.x * 128;      // M block
    const int nb = blockIdx.y * 128;         // N block

    const int kcn = K >> 6;

    const int lrow   = tid >> 3;                     // 0..31
    const int dstx   = ((tid & 7) << 4) ^ ((lrow & 7) << 4);   // swizzled 16B chunk
    const int colelm = (tid & 7) << 3;               // source col (elements)

    const int warp_m = wid & 1;
    const int warp_n = wid >> 1;
    const int arow  = warp_m * 64 + (lane & 15);
    const int axor  = (lane & 7) << 4;
    const int ac8   = (lane >> 4) << 4;
    const int brow  = warp_n * 32 + (lane & 7) + ((lane & 16) >> 1);
    const int bxor  = (lane & 7) << 4;
    const int bc8   = ((lane >> 3) & 1) << 4;

    float acc[4][4][4];
#pragma unroll
    for (int i = 0; i < 4; ++i)
#pragma unroll
        for (int j = 0; j < 4; ++j)
#pragma unroll
            for (int q = 0; q < 4; ++q) acc[i][j][q] = 0.f;

    auto load_stage = [&](int kc, int st) {
        const int kofs = (kc << 6) + colelm;
        uint32_t base = sb + st * STAGE;
#pragma unroll
        for (int j = 0; j < 4; ++j) {
            int row = lrow + (j << 5);
            int gr = tile0 + row; if (gr >= M) gr = M - 1;
            uint32_t rb = base + row * 128 + dstx;
            cp16(rb + ST_AH, Ah + (size_t)gr * K + kofs);
            cp16(rb + ST_AL, Al + (size_t)gr * K + kofs);
            cp16(rb + ST_B,  Bf + (size_t)(nb + row) * K + kofs);
        }
    };

    load_stage(0, 0);
    CP_COMMIT();

    for (int ch = 0; ch < kcn; ++ch) {
        int st = ch & 1;
        if (ch + 1 < kcn) {
            load_stage(ch + 1, st ^ 1);
            CP_COMMIT();
            CP_WAIT1();
        } else {
            CP_WAIT0();
        }
        __syncthreads();

        uint32_t base = sb + st * STAGE;
        // 2 passes from resident tiles: (Ah,B), (Al,B)
#pragma unroll
        for (int p = 0; p < 2; ++p) {
            uint32_t Abase = base + (p ? ST_AL : ST_AH);
            uint32_t Bbase = base + ST_B;
#pragma unroll
            for (int k16 = 0; k16 < 4; ++k16) {
                uint32_t a[4][4], b[2][4];
                int cA = ((k16 << 5) + ac8) ^ axor;
                uint32_t aaddr = Abase + arow * 128 + cA;
#pragma unroll
                for (int tm = 0; tm < 4; ++tm) ldm_x4(a[tm], aaddr + tm * 2048);
                int cB = ((k16 << 5) + bc8) ^ bxor;
                uint32_t baddr = Bbase + brow * 128 + cB;
#pragma unroll
                for (int t2 = 0; t2 < 2; ++t2) ldm_x4(b[t2], baddr + t2 * 2048);
#pragma unroll
                for (int tm = 0; tm < 4; ++tm)
#pragma unroll
                    for (int tn = 0; tn < 4; ++tn)
                        mma16816(acc[tm][tn], a[tm], &b[tn >> 1][(tn & 1) * 2]);
            }
        }
        __syncthreads();
    }

    // ---- epilogue: scale by dinv[row], store f32
    const int mrow0 = tile0 + warp_m * 64 + (lane >> 2);
    const int ncol0 = nb + warp_n * 32 + (lane & 3) * 2;
#pragma unroll
    for (int tm = 0; tm < 4; ++tm) {
        int r0 = mrow0 + tm * 16;
        int r1 = r0 + 8;
        float dv0 = (r0 < M) ? dinv[r0] : 0.f;
        float dv1 = (r1 < M) ? dinv[r1] : 0.f;
#pragma unroll
        for (int tn = 0; tn < 4; ++tn) {
            int c = ncol0 + tn * 8;
            if (r0 < M) {
                float2 o0 = make_float2(acc[tm][tn][0] * dv0, acc[tm][tn][1] * dv0);
                *(float2*)(C + (size_t)r0 * H + c) = o0;
            }
            if (r1 < M) {
                float2 o1 = make_float2(acc[tm][tn][2] * dv1, acc[tm][tn][3] * dv1);
                *(float2*)(C + (size_t)r1 * H + c) = o1;
            }
        }
    }
}

// ---------------- aggregation: pull-model CSR gather ----------------
// layer2==0: out = relu(...) -> split fp16 hi/lo (feeds layer-2 tensor GEMM)
// layer2==1: red.add relu(...) into gsum[batch[d]]
__global__ void __launch_bounds__(256)
agg_kernel(const float* __restrict__ hs, const float* __restrict__ dinv,
           const float* __restrict__ bias,
           __half* __restrict__ outH, __half* __restrict__ outL,
           const int* __restrict__ batch, float* __restrict__ gsum,
           int layer2)
{
    int warp = threadIdx.x >> 5;
    int lane = threadIdx.x & 31;
    int node = blockIdx.x * 8 + warp;          // grid.x = 12500, exact
    int coff = blockIdx.y * 128 + lane * 4;

    const float* hrow = hs + (size_t)node * H + coff;
    float4 acc = *(const float4*)hrow;          // self-loop term

    int beg = g_off[node];
    int cnt = g_ideg[node];
    const int* nb = g_csr + beg;

    int j = 0;
    for (; j + 1 < cnt; j += 2) {
        int s0 = nb[j], s1 = nb[j + 1];
        float4 v0 = *(const float4*)(hs + (size_t)s0 * H + coff);
        float4 v1 = *(const float4*)(hs + (size_t)s1 * H + coff);
        acc.x += v0.x + v1.x;
        acc.y += v0.y + v1.y;
        acc.z += v0.z + v1.z;
        acc.w += v0.w + v1.w;
    }
    if (j < cnt) {
        int s0 = nb[j];
        float4 v0 = *(const float4*)(hs + (size_t)s0 * H + coff);
        acc.x += v0.x; acc.y += v0.y; acc.z += v0.z; acc.w += v0.w;
    }

    float dv = dinv[node];
    const float4 b = *(const float4*)(bias + coff);
    float4 v;
    v.x = fmaxf(fmaf(dv, acc.x, b.x), 0.f);
    v.y = fmaxf(fmaf(dv, acc.y, b.y), 0.f);
    v.z = fmaxf(fmaf(dv, acc.z, b.z), 0.f);
    v.w = fmaxf(fmaf(dv, acc.w, b.w), 0.f);

    if (!layer2) {
        size_t base = (size_t)node * H + coff;
        __half2 h0, l0, h1, l1;
        split2h(v.x, v.y, &h0, &l0);
        split2h(v.z, v.w, &h1, &l1);
        ((__half2*)(outH + base))[0] = h0;
        ((__half2*)(outH + base))[1] = h1;
        ((__half2*)(outL + base))[0] = l0;
        ((__half2*)(outL + base))[1] = l1;
    } else {
        int g = batch[node];
        float* p = gsum + (size_t)g * H + coff;
        asm volatile("red.global.add.v4.f32 [%0], {%1, %2, %3, %4};"
                     :: "l"(p), "f"(v.x), "f"(v.y), "f"(v.z), "f"(v.w) : "memory");
    }
}

// ---------------- classifier: mean, g@Wc+bc, log_softmax(64) ----------------
__global__ void classify_kernel(const float* __restrict__ gsum, const float* __restrict__ gcnt,
                                const float* __restrict__ Wc, const float* __restrict__ bc,
                                float* __restrict__ out)
{
    int gid = blockIdx.x;
    int j = threadIdx.x;                       // 64 threads
    __shared__ float sg[H];
    __shared__ float red2[2];

    float inv = 1.0f / fmaxf(gcnt[gid], 1.0f);
    for (int c = j; c < H; c += 64) sg[c] = gsum[(size_t)gid * H + c] * inv;
    __syncthreads();

    float acc = bc[j];
#pragma unroll
    for (int c = 0; c < H; ++c)
        acc = fmaf(sg[c], Wc[c * 64 + j], acc);

    float m = acc;
#pragma unroll
    for (int o = 16; o; o >>= 1) m = fmaxf(m, __shfl_xor_sync(0xffffffffu, m, o));
    if ((j & 31) == 0) red2[j >> 5] = m;
    __syncthreads();
    m = fmaxf(red2[0], red2[1]);
    __syncthreads();

    float e = expf(acc - m);
    float s = e;
#pragma unroll
    for (int o = 16; o; o >>= 1) s += __shfl_xor_sync(0xffffffffu, s, o);
    if ((j & 31) == 0) red2[j >> 5] = s;
    __syncthreads();
    s = red2[0] + red2[1];

    out[(size_t)gid * 64 + j] = acc - m - logf(s);
}

// ---------------- launch ----------------
extern "C" void kernel_launch(void* const* d_in, const int* in_sizes, int n_in,
                              void* d_out, int out_size)
{
    const float* x     = (const float*)d_in[0];
    const int*   eidx  = (const int*)d_in[1];     // int32 (JAX canonicalized)
    const int*   batch = (const int*)d_in[2];
    const float* W1    = (const float*)d_in[3];
    const float* b1    = (const float*)d_in[4];
    const float* W2    = (const float*)d_in[5];
    const float* b2    = (const float*)d_in[6];
    const float* Wc    = (const float*)d_in[7];
    const float* bc    = (const float*)d_in[8];
    float*       out   = (float*)d_out;

    const int* src = eidx;
    const int* dst = eidx + N_EDGES;

    float *bufA, *dinv, *gsum, *gcnt;
    __half *xh, *xl, *h1h, *h1l, *w1, *w2;
    cudaGetSymbolAddress((void**)&bufA, g_bufA);
    cudaGetSymbolAddress((void**)&dinv, g_dinv);
    cudaGetSymbolAddress((void**)&gsum, g_gsum);
    cudaGetSymbolAddress((void**)&gcnt, g_gcnt);
    cudaGetSymbolAddress((void**)&xh,  g_xh);
    cudaGetSymbolAddress((void**)&xl,  g_xl);
    cudaGetSymbolAddress((void**)&h1h, g_h1h);
    cudaGetSymbolAddress((void**)&h1l, g_h1l);
    cudaGetSymbolAddress((void**)&w1,  g_w1);
    cudaGetSymbolAddress((void**)&w2,  g_w2);

    cudaFuncSetAttribute(gemm_tc, cudaFuncAttributeMaxDynamicSharedMemorySize, GEMM_SMEM);

    // prep + CSR build
    zero_kernel<<<(N_GRAPHS * H) / 256, 256>>>();
    deg_kernel<<<(N_EDGES + 255) / 256, 256>>>(dst);
    scan1_kernel<<<SCAN_NBLK, 256>>>();
    scan2_kernel<<<1, 128>>>();
    scan3_kernel<<<(N_NODES + 255) / 256, 256>>>();
    fill_kernel<<<(N_EDGES + 255) / 256, 256>>>(src, dst);
    prep_kernel<<<(N_NODES + 255) / 256, 256>>>(batch);

    // operand splits
    split_x_kernel<<<(N_NODES * 128 / 4) / 256, 256>>>(x);
    split_w_kernel<<<(128 * 256 + 255) / 256, 256>>>(W1, w1, 128);
    split_w_kernel<<<(256 * 256 + 255) / 256, 256>>>(W2, w2, 256);

    const int ntiles = (N_NODES + 127) / 128;   // 782
    dim3 ggrid(ntiles, 2);                      // N blocks of 128
    dim3 agrid(N_NODES / 8, 2);                 // 12500 x 2 feature chunks

    // layer 1
    gemm_tc<<<ggrid, 256, GEMM_SMEM>>>(xh, xl, w1, dinv, bufA, N_NODES, 128);
    agg_kernel<<<agrid, 256>>>(bufA, dinv, b1, h1h, h1l, batch, gsum, 0);

    // layer 2 (agg fused with relu + mean-pool accumulate)
    gemm_tc<<<ggrid, 256, GEMM_SMEM>>>(h1h, h1l, w2, dinv, bufA, N_NODES, 256);
    agg_kernel<<<agrid, 256>>>(bufA, dinv, b2, nullptr, nullptr, batch, gsum, 1);

    // classifier + log_softmax
    classify_kernel<<<N_GRAPHS, 64>>>(gsum, gcnt, Wc, bc, out);
}

// round 10
// speedup vs baseline: 1.7412x; 1.3698x over previous
#include <cuda_runtime.h>
#include <cuda_fp16.h>
#include <math.h>
#include <stdint.h>

#define N_NODES  100000
#define N_EDGES  1600000
#define N_GRAPHS 2048
#define H        256

#define SCAN_NBLK ((N_NODES + 1023) / 1024)   // 98 blocks of 1024

// ---------------- scratch (device globals; no allocs allowed) ----------------
__device__ int   g_ideg[N_NODES];
__device__ int   g_off[N_NODES];
__device__ int   g_cursor[N_NODES];
__device__ int   g_csr[N_EDGES];
__device__ int   g_bsum[SCAN_NBLK];
__device__ int   g_bscan[SCAN_NBLK];
__device__ float g_dinv[N_NODES];
__device__ float g_gsum[N_GRAPHS * H];
__device__ float g_gcnt[N_GRAPHS];
// fp16 node features (all L2-resident: 25.6 + 51.2 + 51.2 MB)
__device__ __half g_x16[(size_t)N_NODES * 128];   // x as fp16
__device__ __half g_hs[(size_t)N_NODES * H];      // (A @ W) * dinv  (GEMM out)
__device__ __half g_h1[(size_t)N_NODES * H];      // relu(...) layer-1 out
__device__ __half g_w1[256 * 128];
__device__ __half g_w2[256 * 256];

// ================= warp-MMA helpers (sm_80-class, compile for compute_103) ==
__device__ __forceinline__ uint32_t smem_u32(const void* p) {
    uint32_t a;
    asm("{ .reg .u64 t; cvta.to.shared.u64 t, %1; cvt.u32.u64 %0, t; }" : "=r"(a) : "l"(p));
    return a;
}
__device__ __forceinline__ void ldm_x4(uint32_t* r, uint32_t addr) {
    asm volatile("ldmatrix.sync.aligned.m8n8.x4.shared.b16 {%0,%1,%2,%3}, [%4];"
                 : "=r"(r[0]), "=r"(r[1]), "=r"(r[2]), "=r"(r[3]) : "r"(addr));
}
__device__ __forceinline__ void mma16816(float* d, const uint32_t* a, const uint32_t* b) {
    asm volatile("mma.sync.aligned.m16n8k16.row.col.f32.f16.f16.f32 "
                 "{%0,%1,%2,%3}, {%4,%5,%6,%7}, {%8,%9}, {%0,%1,%2,%3};"
                 : "+f"(d[0]), "+f"(d[1]), "+f"(d[2]), "+f"(d[3])
                 : "r"(a[0]), "r"(a[1]), "r"(a[2]), "r"(a[3]), "r"(b[0]), "r"(b[1]));
}
__device__ __forceinline__ void cp16(uint32_t dst, const void* src) {
    asm volatile("cp.async.ca.shared.global [%0], [%1], 16;" :: "r"(dst), "l"(src));
}
#define CP_COMMIT() asm volatile("cp.async.commit_group;" ::: "memory")
#define CP_WAIT1()  asm volatile("cp.async.wait_group 1;" ::: "memory")
#define CP_WAIT0()  asm volatile("cp.async.wait_group 0;" ::: "memory")

// ---------------- prep kernels ----------------

__global__ void zero_kernel() {
    int i = blockIdx.x * blockDim.x + threadIdx.x;     // grid covers N_GRAPHS*H = 524288
    if (i < N_NODES) { g_ideg[i] = 0; g_cursor[i] = 0; }
    if (i < N_GRAPHS * H) g_gsum[i] = 0.f;
    if (i < N_GRAPHS)     g_gcnt[i] = 0.f;
}

__global__ void deg_kernel(const int* __restrict__ dst) {
    int e = blockIdx.x * blockDim.x + threadIdx.x;
    if (e < N_EDGES) atomicAdd(&g_ideg[dst[e]], 1);
}

__global__ void scan1_kernel() {
    __shared__ int sh[256];
    int tid = threadIdx.x;
    int base = blockIdx.x * 1024 + tid * 4;
    int v[4]; int s = 0;
#pragma unroll
    for (int k = 0; k < 4; ++k) {
        int i = base + k;
        v[k] = (i < N_NODES) ? g_ideg[i] : 0;
        s += v[k];
    }
    sh[tid] = s; __syncthreads();
#pragma unroll
    for (int o = 1; o < 256; o <<= 1) {
        int t = (tid >= o) ? sh[tid - o] : 0;
        __syncthreads(); sh[tid] += t; __syncthreads();
    }
    int run = sh[tid] - s;
#pragma unroll
    for (int k = 0; k < 4; ++k) {
        int i = base + k;
        if (i < N_NODES) g_off[i] = run;
        run += v[k];
    }
    if (tid == 255) g_bsum[blockIdx.x] = sh[255];
}

__global__ void scan2_kernel() {
    __shared__ int sh[128];
    int tid = threadIdx.x;
    int v = (tid < SCAN_NBLK) ? g_bsum[tid] : 0;
    sh[tid] = v; __syncthreads();
#pragma unroll
    for (int o = 1; o < 128; o <<= 1) {
        int t = (tid >= o) ? sh[tid - o] : 0;
        __syncthreads(); sh[tid] += t; __syncthreads();
    }
    if (tid < SCAN_NBLK) g_bscan[tid] = sh[tid] - v;
}

__global__ void scan3_kernel() {
    int i = blockIdx.x * blockDim.x + threadIdx.x;
    if (i < N_NODES) g_off[i] += g_bscan[i >> 10];
}

__global__ void fill_kernel(const int* __restrict__ src, const int* __restrict__ dst) {
    int e = blockIdx.x * blockDim.x + threadIdx.x;
    if (e < N_EDGES) {
        int d = dst[e];
        int pos = g_off[d] + atomicAdd(&g_cursor[d], 1);
        g_csr[pos] = src[e];
    }
}

__global__ void prep_kernel(const int* __restrict__ batch) {
    int i = blockIdx.x * blockDim.x + threadIdx.x;
    if (i < N_NODES) {
        g_dinv[i] = rsqrtf((float)g_ideg[i] + 1.0f);
        atomicAdd(&g_gcnt[batch[i]], 1.0f);
    }
}

// convert x (f32) -> fp16; one float4 per thread
__global__ void convert_x_kernel(const float* __restrict__ x) {
    int i = blockIdx.x * blockDim.x + threadIdx.x;     // N_NODES*128/4 threads exactly
    float4 v = ((const float4*)x)[i];
    ((__half2*)g_x16)[i * 2 + 0] = __floats2half2_rn(v.x, v.y);
    ((__half2*)g_x16)[i * 2 + 1] = __floats2half2_rn(v.z, v.w);
}

// transpose W[K,256] -> Wt [256,K] fp16
__global__ void split_w_kernel(const float* __restrict__ W,
                               __half* __restrict__ T, int K) {
    int i = blockIdx.x * blockDim.x + threadIdx.x;     // K*256 threads
    if (i < K * 256) {
        int k = i >> 8;
        int n = i & 255;
        T[n * K + k] = __float2half_rn(W[i]);          // coalesced read
    }
}

// ======== tensor-core GEMM (mma.sync fp16, single pass) =====================
// A: [M, K] fp16 row-major.  Wt: [256, K] fp16 row-major.
// hs[M, 256] fp16 = (A @ Wt^T) * dinv[row].
// CTA tile 128x128, BK=64, double-buffered cp.async.
#define ST_A  0
#define ST_B  16384
#define STAGE 32768
#define GEMM_SMEM (2 * STAGE)   // 65536

__global__ void __launch_bounds__(256, 2)
gemm_tc(const __half* __restrict__ Af, const __half* __restrict__ Bf,
        const float* __restrict__ dinv, __half* __restrict__ C, int M, int K)
{
    extern __shared__ __align__(128) char smem[];
    const uint32_t sb = smem_u32(smem);
    const int tid = threadIdx.x;
    const int wid = tid >> 5;
    const int lane = tid & 31;
    const int tile0 = blockIdx.x * 128;      // M block
    const int nb = blockIdx.y * 128;         // N block

    const int kcn = K >> 6;

    const int lrow   = tid >> 3;                     // 0..31
    const int dstx   = ((tid & 7) << 4) ^ ((lrow & 7) << 4);   // swizzled 16B chunk
    const int colelm = (tid & 7) << 3;               // source col (elements)

    const int warp_m = wid & 1;
    const int warp_n = wid >> 1;
    const int arow  = warp_m * 64 + (lane & 15);
    const int axor  = (lane & 7) << 4;
    const int ac8   = (lane >> 4) << 4;
    const int brow  = warp_n * 32 + (lane & 7) + ((lane & 16) >> 1);
    const int bxor  = (lane & 7) << 4;
    const int bc8   = ((lane >> 3) & 1) << 4;

    float acc[4][4][4];
#pragma unroll
    for (int i = 0; i < 4; ++i)
#pragma unroll
        for (int j = 0; j < 4; ++j)
#pragma unroll
            for (int q = 0; q < 4; ++q) acc[i][j][q] = 0.f;

    auto load_stage = [&](int kc, int st) {
        const int kofs = (kc << 6) + colelm;
        uint32_t base = sb + st * STAGE;
#pragma unroll
        for (int j = 0; j < 4; ++j) {
            int row = lrow + (j << 5);
            int gr = tile0 + row; if (gr >= M) gr = M - 1;
            uint32_t rb = base + row * 128 + dstx;
            cp16(rb + ST_A, Af + (size_t)gr * K + kofs);
            cp16(rb + ST_B, Bf + (size_t)(nb + row) * K + kofs);
        }
    };

    load_stage(0, 0);
    CP_COMMIT();

    for (int ch = 0; ch < kcn; ++ch) {
        int st = ch & 1;
        if (ch + 1 < kcn) {
            load_stage(ch + 1, st ^ 1);
            CP_COMMIT();
            CP_WAIT1();
        } else {
            CP_WAIT0();
        }
        __syncthreads();

        uint32_t Abase = sb + st * STAGE + ST_A;
        uint32_t Bbase = sb + st * STAGE + ST_B;
#pragma unroll
        for (int k16 = 0; k16 < 4; ++k16) {
            uint32_t a[4][4], b[2][4];
            int cA = ((k16 << 5) + ac8) ^ axor;
            uint32_t aaddr = Abase + arow * 128 + cA;
#pragma unroll
            for (int tm = 0; tm < 4; ++tm) ldm_x4(a[tm], aaddr + tm * 2048);
            int cB = ((k16 << 5) + bc8) ^ bxor;
            uint32_t baddr = Bbase + brow * 128 + cB;
#pragma unroll
            for (int t2 = 0; t2 < 2; ++t2) ldm_x4(b[t2], baddr + t2 * 2048);
#pragma unroll
            for (int tm = 0; tm < 4; ++tm)
#pragma unroll
                for (int tn = 0; tn < 4; ++tn)
                    mma16816(acc[tm][tn], a[tm], &b[tn >> 1][(tn & 1) * 2]);
        }
        __syncthreads();
    }

    // ---- epilogue: scale by dinv[row], store fp16
    const int mrow0 = tile0 + warp_m * 64 + (lane >> 2);
    const int ncol0 = nb + warp_n * 32 + (lane & 3) * 2;
#pragma unroll
    for (int tm = 0; tm < 4; ++tm) {
        int r0 = mrow0 + tm * 16;
        int r1 = r0 + 8;
        float dv0 = (r0 < M) ? dinv[r0] : 0.f;
        float dv1 = (r1 < M) ? dinv[r1] : 0.f;
#pragma unroll
        for (int tn = 0; tn < 4; ++tn) {
            int c = ncol0 + tn * 8;
            if (r0 < M)
                *(__half2*)(C + (size_t)r0 * H + c) =
                    __floats2half2_rn(acc[tm][tn][0] * dv0, acc[tm][tn][1] * dv0);
            if (r1 < M)
                *(__half2*)(C + (size_t)r1 * H + c) =
                    __floats2half2_rn(acc[tm][tn][2] * dv1, acc[tm][tn][3] * dv1);
        }
    }
}

// ---------------- aggregation: pull-model CSR gather on fp16 rows ------------
// One warp per node; lane covers 8 cols via one uint4 (8 x fp16).
// layer2==0: out = relu(dinv*sum + bias) -> fp16 h1
// layer2==1: red.add relu(...) into gsum[batch[d]] (f32)
__global__ void __launch_bounds__(256)
agg_kernel(const __half* __restrict__ hs, const float* __restrict__ dinv,
           const float* __restrict__ bias, __half* __restrict__ outH,
           const int* __restrict__ batch, float* __restrict__ gsum,
           int layer2)
{
    int warp = threadIdx.x >> 5;
    int lane = threadIdx.x & 31;
    int node = blockIdx.x * 8 + warp;          // grid.x = 12500, exact
    int coff = lane * 8;                       // 32 lanes x 8 = 256 cols
    size_t rbase = (size_t)node * H + coff;

    float acc[8];
    {
        uint4 u = *(const uint4*)(hs + rbase);  // self-loop term
        const __half2* hp = (const __half2*)&u;
#pragma unroll
        for (int q = 0; q < 4; ++q) {
            float2 f = __half22float2(hp[q]);
            acc[q * 2] = f.x; acc[q * 2 + 1] = f.y;
        }
    }

    int beg = g_off[node];
    int cnt = g_ideg[node];
    const int* nb = g_csr + beg;
    for (int j = 0; j < cnt; ++j) {
        int s = nb[j];
        uint4 u = *(const uint4*)(hs + (size_t)s * H + coff);
        const __half2* hp = (const __half2*)&u;
#pragma unroll
        for (int q = 0; q < 4; ++q) {
            float2 f = __half22float2(hp[q]);
            acc[q * 2] += f.x; acc[q * 2 + 1] += f.y;
        }
    }

    float dv = dinv[node];
    const float4 b0 = *(const float4*)(bias + coff);
    const float4 b1 = *(const float4*)(bias + coff + 4);
    float v[8];
    v[0] = fmaxf(fmaf(dv, acc[0], b0.x), 0.f);
    v[1] = fmaxf(fmaf(dv, acc[1], b0.y), 0.f);
    v[2] = fmaxf(fmaf(dv, acc[2], b0.z), 0.f);
    v[3] = fmaxf(fmaf(dv, acc[3], b0.w), 0.f);
    v[4] = fmaxf(fmaf(dv, acc[4], b1.x), 0.f);
    v[5] = fmaxf(fmaf(dv, acc[5], b1.y), 0.f);
    v[6] = fmaxf(fmaf(dv, acc[6], b1.z), 0.f);
    v[7] = fmaxf(fmaf(dv, acc[7], b1.w), 0.f);

    if (!layer2) {
        __half2 h[4];
#pragma unroll
        for (int q = 0; q < 4; ++q) h[q] = __floats2half2_rn(v[q * 2], v[q * 2 + 1]);
        *(uint4*)(outH + rbase) = *(uint4*)h;
    } else {
        int g = batch[node];
        float* p = gsum + (size_t)g * H + coff;
        asm volatile("red.global.add.v4.f32 [%0], {%1, %2, %3, %4};"
                     :: "l"(p), "f"(v[0]), "f"(v[1]), "f"(v[2]), "f"(v[3]) : "memory");
        asm volatile("red.global.add.v4.f32 [%0], {%1, %2, %3, %4};"
                     :: "l"(p + 4), "f"(v[4]), "f"(v[5]), "f"(v[6]), "f"(v[7]) : "memory");
    }
}

// ---------------- classifier: mean, g@Wc+bc, log_softmax(64) ----------------
__global__ void classify_kernel(const float* __restrict__ gsum, const float* __restrict__ gcnt,
                                const float* __restrict__ Wc, const float* __restrict__ bc,
                                float* __restrict__ out)
{
    int gid = blockIdx.x;
    int j = threadIdx.x;                       // 64 threads
    __shared__ float sg[H];
    __shared__ float red2[2];

    float inv = 1.0f / fmaxf(gcnt[gid], 1.0f);
    for (int c = j; c < H; c += 64) sg[c] = gsum[(size_t)gid * H + c] * inv;
    __syncthreads();

    float acc = bc[j];
#pragma unroll
    for (int c = 0; c < H; ++c)
        acc = fmaf(sg[c], Wc[c * 64 + j], acc);

    float m = acc;
#pragma unroll
    for (int o = 16; o; o >>= 1) m = fmaxf(m, __shfl_xor_sync(0xffffffffu, m, o));
    if ((j & 31) == 0) red2[j >> 5] = m;
    __syncthreads();
    m = fmaxf(red2[0], red2[1]);
    __syncthreads();

    float e = expf(acc - m);
    float s = e;
#pragma unroll
    for (int o = 16; o; o >>= 1) s += __shfl_xor_sync(0xffffffffu, s, o);
    if ((j & 31) == 0) red2[j >> 5] = s;
    __syncthreads();
    s = red2[0] + red2[1];

    out[(size_t)gid * 64 + j] = acc - m - logf(s);
}

// ---------------- launch ----------------
extern "C" void kernel_launch(void* const* d_in, const int* in_sizes, int n_in,
                              void* d_out, int out_size)
{
    const float* x     = (const float*)d_in[0];
    const int*   eidx  = (const int*)d_in[1];     // int32 (JAX canonicalized)
    const int*   batch = (const int*)d_in[2];
    const float* W1    = (const float*)d_in[3];
    const float* b1    = (const float*)d_in[4];
    const float* W2    = (const float*)d_in[5];
    const float* b2    = (const float*)d_in[6];
    const float* Wc    = (const float*)d_in[7];
    const float* bc    = (const float*)d_in[8];
    float*       out   = (float*)d_out;

    const int* src = eidx;
    const int* dst = eidx + N_EDGES;

    float *dinv, *gsum, *gcnt;
    __half *x16, *hs, *h1, *w1, *w2;
    cudaGetSymbolAddress((void**)&dinv, g_dinv);
    cudaGetSymbolAddress((void**)&gsum, g_gsum);
    cudaGetSymbolAddress((void**)&gcnt, g_gcnt);
    cudaGetSymbolAddress((void**)&x16, g_x16);
    cudaGetSymbolAddress((void**)&hs,  g_hs);
    cudaGetSymbolAddress((void**)&h1,  g_h1);
    cudaGetSymbolAddress((void**)&w1,  g_w1);
    cudaGetSymbolAddress((void**)&w2,  g_w2);

    cudaFuncSetAttribute(gemm_tc, cudaFuncAttributeMaxDynamicSharedMemorySize, GEMM_SMEM);

    // prep + CSR build
    zero_kernel<<<(N_GRAPHS * H) / 256, 256>>>();
    deg_kernel<<<(N_EDGES + 255) / 256, 256>>>(dst);
    scan1_kernel<<<SCAN_NBLK, 256>>>();
    scan2_kernel<<<1, 128>>>();
    scan3_kernel<<<(N_NODES + 255) / 256, 256>>>();
    fill_kernel<<<(N_EDGES + 255) / 256, 256>>>(src, dst);
    prep_kernel<<<(N_NODES + 255) / 256, 256>>>(batch);

    // operand conversions
    convert_x_kernel<<<(N_NODES * 128 / 4) / 256, 256>>>(x);
    split_w_kernel<<<(128 * 256 + 255) / 256, 256>>>(W1, w1, 128);
    split_w_kernel<<<(256 * 256 + 255) / 256, 256>>>(W2, w2, 256);

    const int ntiles = (N_NODES + 127) / 128;   // 782
    dim3 ggrid(ntiles, 2);                      // N blocks of 128
    const int agrid = N_NODES / 8;              // 12500

    // layer 1
    gemm_tc<<<ggrid, 256, GEMM_SMEM>>>(x16, w1, dinv, hs, N_NODES, 128);
    agg_kernel<<<agrid, 256>>>(hs, dinv, b1, h1, batch, gsum, 0);

    // layer 2 (agg fused with relu + mean-pool accumulate)
    gemm_tc<<<ggrid, 256, GEMM_SMEM>>>(h1, w2, dinv, hs, N_NODES, 256);
    agg_kernel<<<agrid, 256>>>(hs, dinv, b2, nullptr, batch, gsum, 1);

    // classifier + log_softmax
    classify_kernel<<<N_GRAPHS, 64>>>(gsum, gcnt, Wc, bc, out);
}

// round 11
// speedup vs baseline: 1.9012x; 1.0919x over previous
#include <cuda_runtime.h>
#include <cuda_fp16.h>
#include <math.h>
#include <stdint.h>

#define N_NODES  100000
#define N_EDGES  1600000
#define N_GRAPHS 2048
#define H        256

#define SCAN_NBLK ((N_NODES + 1023) / 1024)   // 98 blocks of 1024

// ---------------- scratch (device globals; no allocs allowed) ----------------
__device__ int   g_ideg[N_NODES];
__device__ int   g_off[N_NODES];
__device__ int   g_cursor[N_NODES];
__device__ int   g_csr[N_EDGES];
__device__ int   g_bsum[SCAN_NBLK];
__device__ int   g_bscan[SCAN_NBLK];
__device__ float g_dinv[N_NODES];
__device__ float g_gsum[N_GRAPHS * H];
__device__ float g_gcnt[N_GRAPHS];
// fp16 node features
__device__ __half g_xs[(size_t)N_NODES * 128];    // dinv * x          (gather src, L1)
__device__ __half g_z1[(size_t)N_NODES * 128];    // dinv*(sum xs)     (gemm1 A)
__device__ __half g_h1s[(size_t)N_NODES * H];     // dinv*relu(z1W1+b1) (gather src, L2)
__device__ __half g_z2[(size_t)N_NODES * H];      // dinv*(sum h1s)    (gemm2 A)
__device__ __half g_w1[256 * 128];
__device__ __half g_w2[256 * 256];

// ================= warp-MMA helpers (sm_80-class, compile for compute_103) ==
__device__ __forceinline__ uint32_t smem_u32(const void* p) {
    uint32_t a;
    asm("{ .reg .u64 t; cvta.to.shared.u64 t, %1; cvt.u32.u64 %0, t; }" : "=r"(a) : "l"(p));
    return a;
}
__device__ __forceinline__ void ldm_x4(uint32_t* r, uint32_t addr) {
    asm volatile("ldmatrix.sync.aligned.m8n8.x4.shared.b16 {%0,%1,%2,%3}, [%4];"
                 : "=r"(r[0]), "=r"(r[1]), "=r"(r[2]), "=r"(r[3]) : "r"(addr));
}
__device__ __forceinline__ void mma16816(float* d, const uint32_t* a, const uint32_t* b) {
    asm volatile("mma.sync.aligned.m16n8k16.row.col.f32.f16.f16.f32 "
                 "{%0,%1,%2,%3}, {%4,%5,%6,%7}, {%8,%9}, {%0,%1,%2,%3};"
                 : "+f"(d[0]), "+f"(d[1]), "+f"(d[2]), "+f"(d[3])
                 : "r"(a[0]), "r"(a[1]), "r"(a[2]), "r"(a[3]), "r"(b[0]), "r"(b[1]));
}
__device__ __forceinline__ void cp16(uint32_t dst, const void* src) {
    asm volatile("cp.async.ca.shared.global [%0], [%1], 16;" :: "r"(dst), "l"(src));
}
#define CP_COMMIT() asm volatile("cp.async.commit_group;" ::: "memory")
#define CP_WAIT1()  asm volatile("cp.async.wait_group 1;" ::: "memory")
#define CP_WAIT0()  asm volatile("cp.async.wait_group 0;" ::: "memory")

// ---------------- prep kernels ----------------

__global__ void zero_kernel() {
    int i = blockIdx.x * blockDim.x + threadIdx.x;     // grid covers N_GRAPHS*H = 524288
    if (i < N_NODES) { g_ideg[i] = 0; g_cursor[i] = 0; }
    if (i < N_GRAPHS * H) g_gsum[i] = 0.f;
    if (i < N_GRAPHS)     g_gcnt[i] = 0.f;
}

__global__ void deg_kernel(const int* __restrict__ dst) {
    int e = blockIdx.x * blockDim.x + threadIdx.x;
    if (e < N_EDGES) atomicAdd(&g_ideg[dst[e]], 1);
}

__global__ void scan1_kernel() {
    __shared__ int sh[256];
    int tid = threadIdx.x;
    int base = blockIdx.x * 1024 + tid * 4;
    int v[4]; int s = 0;
#pragma unroll
    for (int k = 0; k < 4; ++k) {
        int i = base + k;
        v[k] = (i < N_NODES) ? g_ideg[i] : 0;
        s += v[k];
    }
    sh[tid] = s; __syncthreads();
#pragma unroll
    for (int o = 1; o < 256; o <<= 1) {
        int t = (tid >= o) ? sh[tid - o] : 0;
        __syncthreads(); sh[tid] += t; __syncthreads();
    }
    int run = sh[tid] - s;
#pragma unroll
    for (int k = 0; k < 4; ++k) {
        int i = base + k;
        if (i < N_NODES) g_off[i] = run;
        run += v[k];
    }
    if (tid == 255) g_bsum[blockIdx.x] = sh[255];
}

__global__ void scan2_kernel() {
    __shared__ int sh[128];
    int tid = threadIdx.x;
    int v = (tid < SCAN_NBLK) ? g_bsum[tid] : 0;
    sh[tid] = v; __syncthreads();
#pragma unroll
    for (int o = 1; o < 128; o <<= 1) {
        int t = (tid >= o) ? sh[tid - o] : 0;
        __syncthreads(); sh[tid] += t; __syncthreads();
    }
    if (tid < SCAN_NBLK) g_bscan[tid] = sh[tid] - v;
}

__global__ void scan3_kernel() {
    int i = blockIdx.x * blockDim.x + threadIdx.x;
    if (i < N_NODES) g_off[i] += g_bscan[i >> 10];
}

__global__ void fill_kernel(const int* __restrict__ src, const int* __restrict__ dst) {
    int e = blockIdx.x * blockDim.x + threadIdx.x;
    if (e < N_EDGES) {
        int d = dst[e];
        int pos = g_off[d] + atomicAdd(&g_cursor[d], 1);
        g_csr[pos] = src[e];
    }
}

__global__ void prep_kernel(const int* __restrict__ batch) {
    int i = blockIdx.x * blockDim.x + threadIdx.x;
    if (i < N_NODES) {
        g_dinv[i] = rsqrtf((float)g_ideg[i] + 1.0f);
        atomicAdd(&g_gcnt[batch[i]], 1.0f);
    }
}

// xs = dinv[node] * x (fp16); one float4 per thread. Runs AFTER prep.
__global__ void convert_x_kernel(const float* __restrict__ x) {
    int i = blockIdx.x * blockDim.x + threadIdx.x;     // N_NODES*128/4 threads exactly
    float dv = g_dinv[i >> 5];
    float4 v = ((const float4*)x)[i];
    ((__half2*)g_xs)[i * 2 + 0] = __floats2half2_rn(v.x * dv, v.y * dv);
    ((__half2*)g_xs)[i * 2 + 1] = __floats2half2_rn(v.z * dv, v.w * dv);
}

// transpose W[K,256] -> Wt [256,K] fp16
__global__ void split_w_kernel(const float* __restrict__ W,
                               __half* __restrict__ T, int K) {
    int i = blockIdx.x * blockDim.x + threadIdx.x;     // K*256 threads
    if (i < K * 256) {
        int k = i >> 8;
        int n = i & 255;
        T[n * K + k] = __float2half_rn(W[i]);          // coalesced read
    }
}

// ---------------- layer-1 aggregation on xs (128 fp16 cols, 256 B rows) -----
// One warp per node; half-warps process alternating edges (same node -> no
// divergence), 16 lanes x uint4 cover the row. z1 = dinv[d] * (sum + self).
__global__ void __launch_bounds__(256)
agg1_kernel()
{
    int warp = threadIdx.x >> 5;
    int lane = threadIdx.x & 31;
    int node = blockIdx.x * 8 + warp;          // grid.x = 12500, exact
    int half = lane >> 4;
    int coff = (lane & 15) * 8;                // 16 lanes x 8 halfs = 128 cols
    size_t rbase = (size_t)node * 128 + coff;

    float acc[8];
#pragma unroll
    for (int q = 0; q < 8; ++q) acc[q] = 0.f;

    if (half == 0) {                            // self-loop term: xs[d]
        uint4 u = *(const uint4*)(g_xs + rbase);
        const __half2* hp = (const __half2*)&u;
#pragma unroll
        for (int q = 0; q < 4; ++q) {
            float2 f = __half22float2(hp[q]);
            acc[q * 2] += f.x; acc[q * 2 + 1] += f.y;
        }
    }

    int beg = g_off[node];
    int cnt = g_ideg[node];
    const int* nb = g_csr + beg;
    for (int j = half; j < cnt; j += 2) {
        int s = nb[j];
        uint4 u = *(const uint4*)(g_xs + (size_t)s * 128 + coff);
        const __half2* hp = (const __half2*)&u;
#pragma unroll
        for (int q = 0; q < 4; ++q) {
            float2 f = __half22float2(hp[q]);
            acc[q * 2] += f.x; acc[q * 2 + 1] += f.y;
        }
    }

    // combine half-warps (lane i <-> i^16 share coff)
#pragma unroll
    for (int q = 0; q < 8; ++q)
        acc[q] += __shfl_xor_sync(0xffffffffu, acc[q], 16);

    if (half == 0) {
        float dv = g_dinv[node];
        __half2 h[4];
#pragma unroll
        for (int q = 0; q < 4; ++q)
            h[q] = __floats2half2_rn(acc[q * 2] * dv, acc[q * 2 + 1] * dv);
        *(uint4*)(g_z1 + rbase) = *(uint4*)h;
    }
}

// ---------------- layer-2 aggregation on h1s (256 fp16 cols, 512 B rows) ----
// Full warp, lane covers 8 cols via uint4; unroll-2 for MLP.
__global__ void __launch_bounds__(256)
agg2_kernel()
{
    int warp = threadIdx.x >> 5;
    int lane = threadIdx.x & 31;
    int node = blockIdx.x * 8 + warp;          // grid.x = 12500
    int coff = lane * 8;
    size_t rbase = (size_t)node * H + coff;

    float acc[8];
    {
        uint4 u = *(const uint4*)(g_h1s + rbase);   // self-loop term
        const __half2* hp = (const __half2*)&u;
#pragma unroll
        for (int q = 0; q < 4; ++q) {
            float2 f = __half22float2(hp[q]);
            acc[q * 2] = f.x; acc[q * 2 + 1] = f.y;
        }
    }

    int beg = g_off[node];
    int cnt = g_ideg[node];
    const int* nb = g_csr + beg;
    int j = 0;
    for (; j + 1 < cnt; j += 2) {
        int s0 = nb[j], s1 = nb[j + 1];
        uint4 u0 = *(const uint4*)(g_h1s + (size_t)s0 * H + coff);
        uint4 u1 = *(const uint4*)(g_h1s + (size_t)s1 * H + coff);
        const __half2* p0 = (const __half2*)&u0;
        const __half2* p1 = (const __half2*)&u1;
#pragma unroll
        for (int q = 0; q < 4; ++q) {
            float2 f0 = __half22float2(p0[q]);
            float2 f1 = __half22float2(p1[q]);
            acc[q * 2] += f0.x + f1.x;
            acc[q * 2 + 1] += f0.y + f1.y;
        }
    }
    if (j < cnt) {
        int s0 = nb[j];
        uint4 u0 = *(const uint4*)(g_h1s + (size_t)s0 * H + coff);
        const __half2* p0 = (const __half2*)&u0;
#pragma unroll
        for (int q = 0; q < 4; ++q) {
            float2 f0 = __half22float2(p0[q]);
            acc[q * 2] += f0.x; acc[q * 2 + 1] += f0.y;
        }
    }

    float dv = g_dinv[node];
    __half2 h[4];
#pragma unroll
    for (int q = 0; q < 4; ++q)
        h[q] = __floats2half2_rn(acc[q * 2] * dv, acc[q * 2 + 1] * dv);
    *(uint4*)(g_z2 + rbase) = *(uint4*)h;
}

// ======== tensor-core GEMM (mma.sync fp16, single pass) =====================
// A: [M, K] fp16 row-major.  Wt: [256, K] fp16 row-major.
// mode 0: C = dinv[row] * relu(A@Wt^T + bias)  -> fp16 C
// mode 1: red.add relu(A@Wt^T + bias) into gsum[batch[row]]  (mean-pool)
#define ST_A  0
#define ST_B  16384
#define STAGE 32768
#define GEMM_SMEM (2 * STAGE)   // 65536

__global__ void __launch_bounds__(256, 2)
gemm_tc(const __half* __restrict__ Af, const __half* __restrict__ Bf,
        const float* __restrict__ bias, const float* __restrict__ dinv,
        __half* __restrict__ C, const int* __restrict__ batch,
        float* __restrict__ gsum, int M, int K, int mode)
{
    extern __shared__ __align__(128) char smem[];
    const uint32_t sb = smem_u32(smem);
    const int tid = threadIdx.x;
    const int wid = tid >> 5;
    const int lane = tid & 31;
    const int tile0 = blockIdx.x * 128;      // M block
    const int nb = blockIdx.y * 128;         // N block

    const int kcn = K >> 6;

    const int lrow   = tid >> 3;                     // 0..31
    const int dstx   = ((tid & 7) << 4) ^ ((lrow & 7) << 4);   // swizzled 16B chunk
    const int colelm = (tid & 7) << 3;               // source col (elements)

    const int warp_m = wid & 1;
    const int warp_n = wid >> 1;
    const int arow  = warp_m * 64 + (lane & 15);
    const int axor  = (lane & 7) << 4;
    const int ac8   = (lane >> 4) << 4;
    const int brow  = warp_n * 32 + (lane & 7) + ((lane & 16) >> 1);
    const int bxor  = (lane & 7) << 4;
    const int bc8   = ((lane >> 3) & 1) << 4;

    float acc[4][4][4];
#pragma unroll
    for (int i = 0; i < 4; ++i)
#pragma unroll
        for (int j = 0; j < 4; ++j)
#pragma unroll
            for (int q = 0; q < 4; ++q) acc[i][j][q] = 0.f;

    auto load_stage = [&](int kc, int st) {
        const int kofs = (kc << 6) + colelm;
        uint32_t base = sb + st * STAGE;
#pragma unroll
        for (int j = 0; j < 4; ++j) {
            int row = lrow + (j << 5);
            int gr = tile0 + row; if (gr >= M) gr = M - 1;
            uint32_t rb = base + row * 128 + dstx;
            cp16(rb + ST_A, Af + (size_t)gr * K + kofs);
            cp16(rb + ST_B, Bf + (size_t)(nb + row) * K + kofs);
        }
    };

    load_stage(0, 0);
    CP_COMMIT();

    for (int ch = 0; ch < kcn; ++ch) {
        int st = ch & 1;
        if (ch + 1 < kcn) {
            load_stage(ch + 1, st ^ 1);
            CP_COMMIT();
            CP_WAIT1();
        } else {
            CP_WAIT0();
        }
        __syncthreads();

        uint32_t Abase = sb + st * STAGE + ST_A;
        uint32_t Bbase = sb + st * STAGE + ST_B;
#pragma unroll
        for (int k16 = 0; k16 < 4; ++k16) {
            uint32_t a[4][4], b[2][4];
            int cA = ((k16 << 5) + ac8) ^ axor;
            uint32_t aaddr = Abase + arow * 128 + cA;
#pragma unroll
            for (int tm = 0; tm < 4; ++tm) ldm_x4(a[tm], aaddr + tm * 2048);
            int cB = ((k16 << 5) + bc8) ^ bxor;
            uint32_t baddr = Bbase + brow * 128 + cB;
#pragma unroll
            for (int t2 = 0; t2 < 2; ++t2) ldm_x4(b[t2], baddr + t2 * 2048);
#pragma unroll
            for (int tm = 0; tm < 4; ++tm)
#pragma unroll
                for (int tn = 0; tn < 4; ++tn)
                    mma16816(acc[tm][tn], a[tm], &b[tn >> 1][(tn & 1) * 2]);
        }
        __syncthreads();
    }

    // ---- epilogue
    const int mrow0 = tile0 + warp_m * 64 + (lane >> 2);
    const int ncol0 = nb + warp_n * 32 + (lane & 3) * 2;
#pragma unroll
    for (int tm = 0; tm < 4; ++tm) {
        int r0 = mrow0 + tm * 16;
        int r1 = r0 + 8;
#pragma unroll
        for (int tn = 0; tn < 4; ++tn) {
            int c = ncol0 + tn * 8;
            const float2 bb = *(const float2*)(bias + c);
            float v0 = fmaxf(acc[tm][tn][0] + bb.x, 0.f);
            float v1 = fmaxf(acc[tm][tn][1] + bb.y, 0.f);
            float v2 = fmaxf(acc[tm][tn][2] + bb.x, 0.f);
            float v3 = fmaxf(acc[tm][tn][3] + bb.y, 0.f);
            if (mode == 0) {
                if (r0 < M) {
                    float dv0 = dinv[r0];
                    *(__half2*)(C + (size_t)r0 * H + c) =
                        __floats2half2_rn(v0 * dv0, v1 * dv0);
                }
                if (r1 < M) {
                    float dv1 = dinv[r1];
                    *(__half2*)(C + (size_t)r1 * H + c) =
                        __floats2half2_rn(v2 * dv1, v3 * dv1);
                }
            } else {
                if (r0 < M) {
                    float* p = gsum + (size_t)batch[r0] * H + c;
                    asm volatile("red.global.add.v2.f32 [%0], {%1, %2};"
                                 :: "l"(p), "f"(v0), "f"(v1) : "memory");
                }
                if (r1 < M) {
                    float* p = gsum + (size_t)batch[r1] * H + c;
                    asm volatile("red.global.add.v2.f32 [%0], {%1, %2};"
                                 :: "l"(p), "f"(v2), "f"(v3) : "memory");
                }
            }
        }
    }
}

// ---------------- classifier: mean, g@Wc+bc, log_softmax(64) ----------------
__global__ void classify_kernel(const float* __restrict__ gsum, const float* __restrict__ gcnt,
                                const float* __restrict__ Wc, const float* __restrict__ bc,
                                float* __restrict__ out)
{
    int gid = blockIdx.x;
    int j = threadIdx.x;                       // 64 threads
    __shared__ float sg[H];
    __shared__ float red2[2];

    float inv = 1.0f / fmaxf(gcnt[gid], 1.0f);
    for (int c = j; c < H; c += 64) sg[c] = gsum[(size_t)gid * H + c] * inv;
    __syncthreads();

    float acc = bc[j];
#pragma unroll
    for (int c = 0; c < H; ++c)
        acc = fmaf(sg[c], Wc[c * 64 + j], acc);

    float m = acc;
#pragma unroll
    for (int o = 16; o; o >>= 1) m = fmaxf(m, __shfl_xor_sync(0xffffffffu, m, o));
    if ((j & 31) == 0) red2[j >> 5] = m;
    __syncthreads();
    m = fmaxf(red2[0], red2[1]);
    __syncthreads();

    float e = expf(acc - m);
    float s = e;
#pragma unroll
    for (int o = 16; o; o >>= 1) s += __shfl_xor_sync(0xffffffffu, s, o);
    if ((j & 31) == 0) red2[j >> 5] = s;
    __syncthreads();
    s = red2[0] + red2[1];

    out[(size_t)gid * 64 + j] = acc - m - logf(s);
}

// ---------------- launch ----------------
extern "C" void kernel_launch(void* const* d_in, const int* in_sizes, int n_in,
                              void* d_out, int out_size)
{
    const float* x     = (const float*)d_in[0];
    const int*   eidx  = (const int*)d_in[1];     // int32 (JAX canonicalized)
    const int*   batch = (const int*)d_in[2];
    const float* W1    = (const float*)d_in[3];
    const float* b1    = (const float*)d_in[4];
    const float* W2    = (const float*)d_in[5];
    const float* b2    = (const float*)d_in[6];
    const float* Wc    = (const float*)d_in[7];
    const float* bc    = (const float*)d_in[8];
    float*       out   = (float*)d_out;

    const int* src = eidx;
    const int* dst = eidx + N_EDGES;

    float *dinv, *gsum, *gcnt;
    __half *z1, *h1s, *z2, *w1, *w2;
    cudaGetSymbolAddress((void**)&dinv, g_dinv);
    cudaGetSymbolAddress((void**)&gsum, g_gsum);
    cudaGetSymbolAddress((void**)&gcnt, g_gcnt);
    cudaGetSymbolAddress((void**)&z1,  g_z1);
    cudaGetSymbolAddress((void**)&h1s, g_h1s);
    cudaGetSymbolAddress((void**)&z2,  g_z2);
    cudaGetSymbolAddress((void**)&w1,  g_w1);
    cudaGetSymbolAddress((void**)&w2,  g_w2);

    cudaFuncSetAttribute(gemm_tc, cudaFuncAttributeMaxDynamicSharedMemorySize, GEMM_SMEM);

    // prep + CSR build
    zero_kernel<<<(N_GRAPHS * H) / 256, 256>>>();
    deg_kernel<<<(N_EDGES + 255) / 256, 256>>>(dst);
    scan1_kernel<<<SCAN_NBLK, 256>>>();
    scan2_kernel<<<1, 128>>>();
    scan3_kernel<<<(N_NODES + 255) / 256, 256>>>();
    fill_kernel<<<(N_EDGES + 255) / 256, 256>>>(src, dst);
    prep_kernel<<<(N_NODES + 255) / 256, 256>>>(batch);

    // operand conversions (convert_x needs dinv -> after prep)
    convert_x_kernel<<<(N_NODES * 128 / 4) / 256, 256>>>(x);
    split_w_kernel<<<(128 * 256 + 255) / 256, 256>>>(W1, w1, 128);
    split_w_kernel<<<(256 * 256 + 255) / 256, 256>>>(W2, w2, 256);

    const int ntiles = (N_NODES + 127) / 128;   // 782
    dim3 ggrid(ntiles, 2);                      // N blocks of 128
    const int agrid = N_NODES / 8;              // 12500

    // layer 1: aggregate xs first (256 B rows), then GEMM w/ relu+dinv epilogue
    agg1_kernel<<<agrid, 256>>>();
    gemm_tc<<<ggrid, 256, GEMM_SMEM>>>(z1, w1, b1, dinv, h1s, nullptr, nullptr,
                                       N_NODES, 128, 0);

    // layer 2: aggregate h1s, then GEMM w/ relu + fused mean-pool epilogue
    agg2_kernel<<<agrid, 256>>>();
    gemm_tc<<<ggrid, 256, GEMM_SMEM>>>(z2, w2, b2, nullptr, nullptr, batch, gsum,
                                       N_NODES, 256, 1);

    // classifier + log_softmax
    classify_kernel<<<N_GRAPHS, 64>>>(gsum, gcnt, Wc, bc, out);
}